// round 9
// baseline (speedup 1.0000x reference)
#include <cuda_runtime.h>
#include <math.h>

// Problem constants
#define B_ 8
#define L_ 512
#define K_ 512
#define D_ 64
#define M_ 64
#define N_ 64
#define P_ 64

#define TL 8            // l-rows per block in score_tmp kernel
#define SWS 516         // sW row stride in floats (bank-spread: 516 mod 32 = 4)

typedef unsigned long long ull;

// Packed f32x2 helpers (Blackwell sm_103a)
#define FMA2ACC(acc, a, b) \
    asm("fma.rn.f32x2 %0, %1, %2, %0;" : "+l"(acc) : "l"(a), "l"(b))

__device__ __forceinline__ ull f2pack(float lo, float hi) {
    ull u; asm("mov.b64 %0, {%1, %2};" : "=l"(u) : "f"(lo), "f"(hi)); return u;
}
__device__ __forceinline__ ull fdup(float v) {
    ull u; asm("mov.b64 %0, {%1, %1};" : "=l"(u) : "f"(v)); return u;
}
__device__ __forceinline__ float2 f2unpack(ull u) {
    float2 v; asm("mov.b64 {%0, %1}, %2;" : "=f"(v.x), "=f"(v.y) : "l"(u)); return v;
}

// Scratch
__device__ float g_vkc[B_ * K_ * N_];   // vkc[b,k,n] (1 MB)
__device__ float g_tmp[B_ * L_ * N_];   // tmp[b,l,n] (1 MB)

// ---------------------------------------------------------------------------
// Kernel 1: vkc[b,k,n] = sum_p vk[b,k,p,n] * vexp[b,k,p]   (streams vk once)
// ---------------------------------------------------------------------------
__global__ __launch_bounds__(64) void vkc_kernel(const float* __restrict__ vk,
                                                 const float* __restrict__ vexp) {
    const int bk = blockIdx.x;
    const int n = threadIdx.x;

    __shared__ float se[P_];
    se[n] = vexp[(size_t)bk * P_ + n];
    __syncthreads();

    const float* base = vk + (size_t)bk * P_ * N_ + n;
    float acc = 0.f;
#pragma unroll
    for (int p = 0; p < P_; ++p) {
        acc = fmaf(base[p * N_], se[p], acc);
    }
    g_vkc[(size_t)bk * N_ + n] = acc;
}

// ---------------------------------------------------------------------------
// Kernel 2: scores + softmax + tmp.  One block = 8 l-rows of one b.
// grid = 512 blocks, 256 threads.
//
// Phase A (register-resident): thread = (k_local = t>>3, dg = t&7).
//   Thread holds q[l][dg*8 .. dg*8+8) for all 8 l in registers; loads its
//   K slice straight from global (L2-resident, coalesced: 8 lanes x 32B
//   contiguous per k-row). Partial dots reduced over the 8-lane dg group.
// Phase B: tmp[l][n] = inv * sum_k e[l][k]*vkc[b][k][n], f32x2 FMAs.
// ---------------------------------------------------------------------------
__global__ __launch_bounds__(256) void score_tmp_kernel(const float* __restrict__ q,
                                                        const float* __restrict__ kmat,
                                                        const float* __restrict__ scale_p,
                                                        float* __restrict__ tmp_out) {
    __shared__ float sW[TL * SWS];      // 16512 B : scores -> exp weights
    __shared__ float sQ[TL * D_];       //  2048 B
    __shared__ float sTmpP[2][TL * N_]; //  4096 B : k-half partials
    __shared__ float sInv[TL];

    const int t = threadIdx.x;
    const int warp = t >> 5;
    const int lane = t & 31;
    const int blk = blockIdx.x;         // b*64 + ltile
    const int b = blk >> 6;
    const int bl8 = blk * 8;            // = b*L_ + ltile*8
    const float scl = *scale_p;

    // ---- load Q tile (8 rows x 64 floats, contiguous) ----
    if (t < 128) ((float4*)sQ)[t] = ((const float4*)q)[(size_t)bl8 * 16 + t];
    __syncthreads();

    // ---- Phase A ----
    {
        const int dg = t & 7;           // d-octet 0..7
        const int kl = t >> 3;          // k sub-index 0..31

        // q registers: 8 rows x 4 packed f32x2 (8 d-floats each)
        ull qr[8][4];
#pragma unroll
        for (int l = 0; l < 8; ++l) {
            float4 a = *(const float4*)(sQ + l * D_ + dg * 8);
            float4 c = *(const float4*)(sQ + l * D_ + dg * 8 + 4);
            qr[l][0] = f2pack(a.x, a.y);
            qr[l][1] = f2pack(a.z, a.w);
            qr[l][2] = f2pack(c.x, c.y);
            qr[l][3] = f2pack(c.z, c.w);
        }

        const float4* kg = (const float4*)(kmat + (size_t)b * K_ * D_);
#pragma unroll 2
        for (int it = 0; it < 16; ++it) {
            const int kk = it * 32 + kl;
            float4 k0 = kg[(size_t)kk * 16 + dg * 2];
            float4 k1 = kg[(size_t)kk * 16 + dg * 2 + 1];
            ull kv0 = f2pack(k0.x, k0.y);
            ull kv1 = f2pack(k0.z, k0.w);
            ull kv2 = f2pack(k1.x, k1.y);
            ull kv3 = f2pack(k1.z, k1.w);

            float mine = 0.f;
#pragma unroll
            for (int l = 0; l < 8; ++l) {
                ull a2 = 0ULL;
                FMA2ACC(a2, kv0, qr[l][0]);
                FMA2ACC(a2, kv1, qr[l][1]);
                FMA2ACC(a2, kv2, qr[l][2]);
                FMA2ACC(a2, kv3, qr[l][3]);
                float2 f = f2unpack(a2);
                float v = f.x + f.y;
                v += __shfl_xor_sync(0xFFFFFFFFu, v, 1);
                v += __shfl_xor_sync(0xFFFFFFFFu, v, 2);
                v += __shfl_xor_sync(0xFFFFFFFFu, v, 4);
                if (dg == l) mine = v;
            }
            sW[dg * SWS + kk] = mine * scl;   // row l=dg, conflict-free banks
        }
    }
    __syncthreads();

    // ---- softmax, warp w owns row w ----
    {
        float* row = sW + warp * SWS;
        float mx = -1e30f;
#pragma unroll
        for (int i = 0; i < K_ / 32; ++i) mx = fmaxf(mx, row[lane + i * 32]);
#pragma unroll
        for (int o = 16; o; o >>= 1) mx = fmaxf(mx, __shfl_xor_sync(0xFFFFFFFFu, mx, o));
        float s = 0.f;
#pragma unroll
        for (int i = 0; i < K_ / 32; ++i) {
            float e = __expf(row[lane + i * 32] - mx);
            row[lane + i * 32] = e;
            s += e;
        }
#pragma unroll
        for (int o = 16; o; o >>= 1) s += __shfl_xor_sync(0xFFFFFFFFu, s, o);
        if (lane == 0) sInv[warp] = 1.f / s;
    }
    __syncthreads();

    // ---- Phase B: tmp partials, f32x2 ----
    {
        const int n4 = t & 15;
        const int l = (t >> 4) & 7;
        const int kh = t >> 7;
        const float4* vkc4 = (const float4*)(g_vkc + ((size_t)b * K_ + kh * 256) * N_) + n4;
        const float* wrow = sW + l * SWS + kh * 256;
        ull aX0 = 0ULL, aX1 = 0ULL, aY0 = 0ULL, aY1 = 0ULL;
#pragma unroll 4
        for (int k = 0; k < 256; k += 2) {
            float2 wv = *(const float2*)(wrow + k);
            float4 v0 = vkc4[(size_t)k * 16];
            float4 v1 = vkc4[(size_t)(k + 1) * 16];
            ull w0 = fdup(wv.x);
            ull w1 = fdup(wv.y);
            FMA2ACC(aX0, w0, f2pack(v0.x, v0.y));
            FMA2ACC(aX1, w0, f2pack(v0.z, v0.w));
            FMA2ACC(aY0, w1, f2pack(v1.x, v1.y));
            FMA2ACC(aY1, w1, f2pack(v1.z, v1.w));
        }
        float2 x0 = f2unpack(aX0), x1 = f2unpack(aX1);
        float2 y0 = f2unpack(aY0), y1 = f2unpack(aY1);
        float4 acc = make_float4(x0.x + y0.x, x0.y + y0.y, x1.x + y1.x, x1.y + y1.y);
        ((float4*)(sTmpP[kh] + l * N_))[n4] = acc;
    }
    __syncthreads();

    // ---- combine halves, apply 1/sum, write tmp to global ----
    if (t < 128) {
        const int l = t >> 4, n4 = t & 15;
        float4 a = ((float4*)(sTmpP[0] + l * N_))[n4];
        float4 c = ((float4*)(sTmpP[1] + l * N_))[n4];
        const float inv = sInv[l];
        float4 r = make_float4((a.x + c.x) * inv, (a.y + c.y) * inv,
                               (a.z + c.z) * inv, (a.w + c.w) * inv);
        ((float4*)(tmp_out + ((size_t)bl8 + l) * N_))[n4] = r;
    }
}

// ---------------------------------------------------------------------------
// Kernel 3: out = LayerNorm(q + vq . tmp).  Streams vq (67 MB) coalesced.
// grid = 2048 blocks x 256 threads; each 128-thread half handles one (b,l).
// ---------------------------------------------------------------------------
__global__ __launch_bounds__(256) void out_kernel(const float* __restrict__ q,
                                                  const float* __restrict__ vq,
                                                  const float* __restrict__ gamma,
                                                  const float* __restrict__ beta,
                                                  float* __restrict__ out) {
    __shared__ float sTmp[2][N_];
    __shared__ float sQ[2][D_];
    __shared__ float sAttn[2][M_];

    const int t = threadIdx.x;
    const int h = t >> 7;               // which row-half of the block
    const int tt = t & 127;
    const int bl = blockIdx.x * 2 + h;  // global (b*L + l)

    // stage tmp row + q row
    if (tt < 64) sTmp[h][tt] = g_tmp[(size_t)bl * N_ + tt];
    else         sQ[h][tt - 64] = q[(size_t)bl * D_ + (tt - 64)];
    __syncthreads();

    // attn[m] = vq[bl,m,:] . tmp ;  thread covers float4 n4 = tt&15 of
    // M-rows (tt>>4) + 8j.  Loads: warp = 512B contiguous, 8 independent.
    {
        const int n4 = tt & 15;
        float4 tv = ((const float4*)sTmp[h])[n4];
        ull tv01 = f2pack(tv.x, tv.y);
        ull tv23 = f2pack(tv.z, tv.w);
        const float4* vq4 = (const float4*)vq + (size_t)bl * (M_ * N_ / 4);

        float4 v[8];
#pragma unroll
        for (int j = 0; j < 8; ++j) v[j] = vq4[tt + 128 * j];

#pragma unroll
        for (int j = 0; j < 8; ++j) {
            ull a2 = 0ULL;
            FMA2ACC(a2, f2pack(v[j].x, v[j].y), tv01);
            FMA2ACC(a2, f2pack(v[j].z, v[j].w), tv23);
            float2 f = f2unpack(a2);
            float d = f.x + f.y;
            d += __shfl_xor_sync(0xFFFFFFFFu, d, 1);
            d += __shfl_xor_sync(0xFFFFFFFFu, d, 2);
            d += __shfl_xor_sync(0xFFFFFFFFu, d, 4);
            d += __shfl_xor_sync(0xFFFFFFFFu, d, 8);
            if (n4 == 0) sAttn[h][(tt >> 4) + 8 * j] = d;
        }
    }
    __syncthreads();

    // LayerNorm over M=64: warp 0 (h=0) / warp 4 (h=1), lanes cover m, m+32
    if (tt < 32) {
        const int lane = tt;
        const float x0 = sQ[h][lane] + sAttn[h][lane];
        const float x1 = sQ[h][lane + 32] + sAttn[h][lane + 32];
        float s = x0 + x1, ss = x0 * x0 + x1 * x1;
#pragma unroll
        for (int o = 16; o; o >>= 1) {
            s += __shfl_xor_sync(0xFFFFFFFFu, s, o);
            ss += __shfl_xor_sync(0xFFFFFFFFu, ss, o);
        }
        const float mu = s * (1.f / 64.f);
        const float var = ss * (1.f / 64.f) - mu * mu;
        const float r = rsqrtf(var + 1e-3f);
        out[(size_t)bl * M_ + lane] = (x0 - mu) * r * gamma[lane] + beta[lane];
        out[(size_t)bl * M_ + lane + 32] =
            (x1 - mu) * r * gamma[lane + 32] + beta[lane + 32];
    }
}

// ---------------------------------------------------------------------------
extern "C" void kernel_launch(void* const* d_in, const int* in_sizes, int n_in,
                              void* d_out, int out_size) {
    const float* q     = (const float*)d_in[0];
    const float* k     = (const float*)d_in[1];
    const float* vq    = (const float*)d_in[2];
    const float* vk    = (const float*)d_in[3];
    const float* vexp  = (const float*)d_in[4];
    const float* scale = (const float*)d_in[5];
    const float* gamma = (const float*)d_in[6];
    const float* beta  = (const float*)d_in[7];
    float* out = (float*)d_out;

    float* tmp_ptr;
    cudaGetSymbolAddress((void**)&tmp_ptr, g_tmp);

    vkc_kernel<<<B_ * K_, 64>>>(vk, vexp);
    score_tmp_kernel<<<B_ * L_ / TL, 256>>>(q, k, scale, tmp_ptr);
    out_kernel<<<B_ * L_ / 2, 256>>>(q, vq, gamma, beta, out);
}